// round 1
// baseline (speedup 1.0000x reference)
#include <cuda_runtime.h>
#include <cuda_bf16.h>

#define N_NODES 50000
#define N_EDGES 800000
#define N_FEAT  512
#define N_HID   256
#define N_LAYER 4
#define N_CLASS 40
#define JK_DIM  (N_HID * N_LAYER)   // 1024

// ---------------- scratch (device globals; no allocation allowed) ----------
__device__ int   g_cnt[N_NODES];
__device__ int   g_off[N_NODES + 1];
__device__ int   g_cur[N_NODES];
__device__ int   g_srt_src[N_EDGES];
__device__ float g_srt_coef[N_EDGES];
__device__ float g_dinv[N_NODES];
__device__ float g_selfn[N_NODES];
__device__ float g_hw [N_NODES * N_HID];   // 51.2 MB
__device__ float g_lin[N_NODES * N_HID];   // 51.2 MB
__device__ float g_jk [N_NODES * JK_DIM];  // 204.8 MB

// ---------------- preprocessing kernels -----------------------------------
__global__ void zero_cnt_kernel() {
    int i = blockIdx.x * blockDim.x + threadIdx.x;
    if (i < N_NODES) g_cnt[i] = 0;
}

__global__ void count_kernel(const int* __restrict__ dst) {
    int i = blockIdx.x * blockDim.x + threadIdx.x;
    if (i < N_EDGES) atomicAdd(&g_cnt[dst[i]], 1);
}

__global__ void dinv_kernel() {
    int i = blockIdx.x * blockDim.x + threadIdx.x;
    if (i < N_NODES) {
        float deg = (float)g_cnt[i] + 1.0f;
        float di  = rsqrtf(deg);
        g_dinv[i]  = di;
        g_selfn[i] = di * di;
    }
}

// single-block chunked Hillis-Steele exclusive scan over g_cnt -> g_off,g_cur
__global__ void scan_kernel() {
    __shared__ int sh[1024];
    __shared__ int carry_sh;
    int t = threadIdx.x;
    if (t == 0) carry_sh = 0;
    __syncthreads();
    for (int base = 0; base < N_NODES; base += 1024) {
        int i = base + t;
        int x = (i < N_NODES) ? g_cnt[i] : 0;
        sh[t] = x;
        __syncthreads();
        for (int off = 1; off < 1024; off <<= 1) {
            int v = (t >= off) ? sh[t - off] : 0;
            __syncthreads();
            sh[t] += v;
            __syncthreads();
        }
        int excl = carry_sh + sh[t] - x;
        if (i < N_NODES) { g_off[i] = excl; g_cur[i] = excl; }
        __syncthreads();
        if (t == 1023) carry_sh += sh[1023];
        __syncthreads();
    }
    if (t == 0) g_off[N_NODES] = carry_sh;
}

__global__ void fill_kernel(const int* __restrict__ src, const int* __restrict__ dst) {
    int i = blockIdx.x * blockDim.x + threadIdx.x;
    if (i < N_EDGES) {
        int s = src[i], d = dst[i];
        int pos = atomicAdd(&g_cur[d], 1);
        g_srt_src[pos]  = s;
        g_srt_coef[pos] = g_dinv[s] * g_dinv[d];
    }
}

// ---------------- SGEMM: C[M,N] = A[M,K] @ B[K,N] (row-major, strided) ----
#define BM 128
#define BN 128
#define BKK 8
#define TM 8
#define TN 8

__global__ __launch_bounds__(256)
void sgemm_kernel(const float* __restrict__ A, const float* __restrict__ B,
                  float* __restrict__ C, int M, int N, int K,
                  int lda, int ldb, int ldc)
{
    __shared__ float As[BKK][BM];
    __shared__ float Bs[BKK][BN];

    int tid  = threadIdx.x;
    int row0 = blockIdx.y * BM;
    int col0 = blockIdx.x * BN;
    int tx = tid & 15;        // 0..15 -> column group
    int ty = tid >> 4;        // 0..15 -> row group

    float acc[TM][TN];
    #pragma unroll
    for (int i = 0; i < TM; i++)
        #pragma unroll
        for (int j = 0; j < TN; j++) acc[i][j] = 0.f;

    for (int k0 = 0; k0 < K; k0 += BKK) {
        #pragma unroll
        for (int i = 0; i < 4; i++) {
            int lid = tid * 4 + i;            // 0..1023
            int r  = lid >> 3;                // 0..127
            int kk = lid & 7;                 // 0..7
            int gr = row0 + r;
            As[kk][r] = (gr < M) ? A[(long)gr * lda + k0 + kk] : 0.f;
        }
        #pragma unroll
        for (int i = 0; i < 4; i++) {
            int lid = tid * 4 + i;
            int kk = lid >> 7;                // 0..7
            int c  = lid & 127;               // 0..127
            int gc = col0 + c;
            Bs[kk][c] = (gc < N) ? B[(long)(k0 + kk) * ldb + gc] : 0.f;
        }
        __syncthreads();

        #pragma unroll
        for (int kk = 0; kk < BKK; kk++) {
            float a[TM], b[TN];
            #pragma unroll
            for (int i = 0; i < TM; i++) a[i] = As[kk][ty * TM + i];
            #pragma unroll
            for (int j = 0; j < TN; j++) b[j] = Bs[kk][tx * TN + j];
            #pragma unroll
            for (int i = 0; i < TM; i++)
                #pragma unroll
                for (int j = 0; j < TN; j++) acc[i][j] += a[i] * b[j];
        }
        __syncthreads();
    }

    #pragma unroll
    for (int i = 0; i < TM; i++) {
        int gr = row0 + ty * TM + i;
        if (gr >= M) continue;
        #pragma unroll
        for (int j = 0; j < TN; j++) {
            int gc = col0 + tx * TN + j;
            if (gc < N) C[(long)gr * ldc + gc] = acc[i][j];
        }
    }
}

// ---------------- fused GCN aggregation epilogue ---------------------------
// out(jk slot) = relu( sum_e coef*hw[src_e] + selfn[n]*hw[n] + gcb + lin + linb )
__global__ __launch_bounds__(N_HID)
void agg_kernel(const float* __restrict__ hw, const float* __restrict__ lin,
                const float* __restrict__ gcb, const float* __restrict__ linb,
                int slot)
{
    int n = blockIdx.x;
    int f = threadIdx.x;                     // 0..255
    int beg = g_off[n], end = g_off[n + 1];

    float acc = 0.f;
    int e = beg;
    for (; e + 3 < end; e += 4) {
        int   s0 = g_srt_src[e],     s1 = g_srt_src[e + 1];
        int   s2 = g_srt_src[e + 2], s3 = g_srt_src[e + 3];
        float c0 = g_srt_coef[e],     c1 = g_srt_coef[e + 1];
        float c2 = g_srt_coef[e + 2], c3 = g_srt_coef[e + 3];
        acc += c0 * hw[s0 * N_HID + f];
        acc += c1 * hw[s1 * N_HID + f];
        acc += c2 * hw[s2 * N_HID + f];
        acc += c3 * hw[s3 * N_HID + f];
    }
    for (; e < end; e++)
        acc += g_srt_coef[e] * hw[g_srt_src[e] * N_HID + f];

    float r = acc + g_selfn[n] * hw[n * N_HID + f] + gcb[f]
              + lin[n * N_HID + f] + linb[f];
    g_jk[(long)n * JK_DIM + slot * N_HID + f] = fmaxf(r, 0.f);
}

// ---------------- output GEMM: [50000,1024] @ [1024,40] + bias ------------
__global__ __launch_bounds__(320)
void out_gemm_kernel(const float* __restrict__ W, const float* __restrict__ b,
                     float* __restrict__ out)
{
    __shared__ float shA[32][65];
    __shared__ float shW[64][N_CLASS];
    int t = threadIdx.x;                 // 0..319
    int row0 = blockIdx.x * 32;
    int c  = t % N_CLASS;                // 0..39
    int r8 = t / N_CLASS;                // 0..7

    float acc[4] = {0.f, 0.f, 0.f, 0.f};

    for (int k0 = 0; k0 < JK_DIM; k0 += 64) {
        for (int l = t; l < 32 * 64; l += 320) {
            int r = l >> 6, kk = l & 63;
            int gr = row0 + r;
            shA[r][kk] = (gr < N_NODES) ? g_jk[(long)gr * JK_DIM + k0 + kk] : 0.f;
        }
        for (int l = t; l < 64 * N_CLASS; l += 320) {
            int kk = l / N_CLASS, cc = l % N_CLASS;
            shW[kk][cc] = W[(k0 + kk) * N_CLASS + cc];
        }
        __syncthreads();
        #pragma unroll 8
        for (int kk = 0; kk < 64; kk++) {
            float w = shW[kk][c];
            #pragma unroll
            for (int j = 0; j < 4; j++)
                acc[j] += shA[r8 + 8 * j][kk] * w;
        }
        __syncthreads();
    }

    float bb = b[c];
    #pragma unroll
    for (int j = 0; j < 4; j++) {
        int gr = row0 + r8 + 8 * j;
        if (gr < N_NODES) out[gr * N_CLASS + c] = acc[j] + bb;
    }
}

// ---------------- launch ---------------------------------------------------
extern "C" void kernel_launch(void* const* d_in, const int* in_sizes, int n_in,
                              void* d_out, int out_size)
{
    const float* x        = (const float*)d_in[0];
    const int*   edge     = (const int*)  d_in[1];
    const float* in_gc_W  = (const float*)d_in[2];
    const float* in_gc_b  = (const float*)d_in[3];
    const float* in_lin_W = (const float*)d_in[4];
    const float* in_lin_b = (const float*)d_in[5];
    const float* convs_W  = (const float*)d_in[6];
    const float* convs_b  = (const float*)d_in[7];
    const float* lins_W   = (const float*)d_in[8];
    const float* lins_b   = (const float*)d_in[9];
    const float* out_W    = (const float*)d_in[10];
    const float* out_b    = (const float*)d_in[11];
    float*       out      = (float*)d_out;

    const int* src = edge;
    const int* dst = edge + N_EDGES;

    float* p_hw; float* p_lin;
    cudaGetSymbolAddress((void**)&p_hw,  g_hw);
    cudaGetSymbolAddress((void**)&p_lin, g_lin);
    float* p_jk;
    cudaGetSymbolAddress((void**)&p_jk,  g_jk);

    // --- preprocessing: degrees, normalization, CSR-by-dst sort ---
    zero_cnt_kernel<<<(N_NODES + 255) / 256, 256>>>();
    count_kernel<<<(N_EDGES + 255) / 256, 256>>>(dst);
    dinv_kernel<<<(N_NODES + 255) / 256, 256>>>();
    scan_kernel<<<1, 1024>>>();
    fill_kernel<<<(N_EDGES + 255) / 256, 256>>>(src, dst);

    dim3 gemm_grid((N_HID + BN - 1) / BN, (N_NODES + BM - 1) / BM);

    // --- layer 0: input 512 -> 256 ---
    sgemm_kernel<<<gemm_grid, 256>>>(x, in_gc_W,  p_hw,  N_NODES, N_HID, N_FEAT,
                                     N_FEAT, N_HID, N_HID);
    sgemm_kernel<<<gemm_grid, 256>>>(x, in_lin_W, p_lin, N_NODES, N_HID, N_FEAT,
                                     N_FEAT, N_HID, N_HID);
    agg_kernel<<<N_NODES, N_HID>>>(p_hw, p_lin, in_gc_b, in_lin_b, 0);

    // --- layers 1..3: 256 -> 256, input read from jk slab (lda = 1024) ---
    for (int i = 0; i < N_LAYER - 1; i++) {
        const float* h = p_jk + i * N_HID;
        sgemm_kernel<<<gemm_grid, 256>>>(h, convs_W + i * N_HID * N_HID, p_hw,
                                         N_NODES, N_HID, N_HID,
                                         JK_DIM, N_HID, N_HID);
        sgemm_kernel<<<gemm_grid, 256>>>(h, lins_W + i * N_HID * N_HID, p_lin,
                                         N_NODES, N_HID, N_HID,
                                         JK_DIM, N_HID, N_HID);
        agg_kernel<<<N_NODES, N_HID>>>(p_hw, p_lin,
                                       convs_b + i * N_HID, lins_b + i * N_HID,
                                       i + 1);
    }

    // --- output projection ---
    out_gemm_kernel<<<(N_NODES + 31) / 32, 320>>>(out_W, out_b, out);
}

// round 3
// speedup vs baseline: 2.4681x; 2.4681x over previous
#include <cuda_runtime.h>
#include <cuda_bf16.h>

#define N_NODES 50000
#define N_EDGES 800000
#define N_FEAT  512
#define N_HID   256
#define N_LAYER 4
#define N_CLASS 40
#define JK_DIM  (N_HID * N_LAYER)   // 1024

// ---------------- scratch (device globals; no allocation allowed) ----------
__device__ int   g_cnt[N_NODES];
__device__ int   g_off[N_NODES + 1];
__device__ int   g_cur[N_NODES];
__device__ int   g_srt_src[N_EDGES];
__device__ float g_srt_coef[N_EDGES];
__device__ float g_dinv[N_NODES];
__device__ float g_selfn[N_NODES];
__device__ __align__(256) float g_hw [N_NODES * N_HID];            // 51.2 MB
__device__ __align__(256) float g_lin[N_NODES * N_HID];            // 51.2 MB
__device__ __align__(256) float g_jk [(size_t)N_NODES * JK_DIM];   // 204.8 MB
// bf16 hi/lo packed operands
__device__ __align__(256) __nv_bfloat16 g_xh[(size_t)N_NODES * N_FEAT];
__device__ __align__(256) __nv_bfloat16 g_xl[(size_t)N_NODES * N_FEAT];
__device__ __align__(256) __nv_bfloat16 g_Ah[(size_t)N_NODES * N_HID];
__device__ __align__(256) __nv_bfloat16 g_Al[(size_t)N_NODES * N_HID];
__device__ __align__(256) __nv_bfloat16 g_Bh[4 * 512 * 512];
__device__ __align__(256) __nv_bfloat16 g_Bl[4 * 512 * 512];

// ---------------- helpers ---------------------------------------------------
__device__ __forceinline__ unsigned su32(const void* p) {
    unsigned a;
    asm("{ .reg .u64 t; cvta.to.shared.u64 t, %1; cvt.u32.u64 %0, t; }"
        : "=r"(a) : "l"(p));
    return a;
}

__device__ __forceinline__ void cp16(unsigned d, const void* s, unsigned sz) {
    asm volatile("cp.async.cg.shared.global [%0], [%1], 16, %2;"
                 :: "r"(d), "l"(s), "r"(sz) : "memory");
}
#define CP_COMMIT asm volatile("cp.async.commit_group;" ::: "memory")
#define CP_WAIT1  asm volatile("cp.async.wait_group 1;" ::: "memory")
#define CP_WAIT0  asm volatile("cp.async.wait_group 0;" ::: "memory")

#define LDSM4(r, a) \
    asm volatile("ldmatrix.sync.aligned.m8n8.x4.shared.b16 {%0,%1,%2,%3}, [%4];" \
        : "=r"((r)[0]), "=r"((r)[1]), "=r"((r)[2]), "=r"((r)[3]) : "r"(a))

__device__ __forceinline__ void mma_bf16(float* c, const unsigned* a,
                                         unsigned b0, unsigned b1) {
    asm volatile("mma.sync.aligned.m16n8k16.row.col.f32.bf16.bf16.f32 "
        "{%0,%1,%2,%3}, {%4,%5,%6,%7}, {%8,%9}, {%0,%1,%2,%3};"
        : "+f"(c[0]), "+f"(c[1]), "+f"(c[2]), "+f"(c[3])
        : "r"(a[0]), "r"(a[1]), "r"(a[2]), "r"(a[3]), "r"(b0), "r"(b1));
}

// ---------------- preprocessing kernels -----------------------------------
__global__ void zero_cnt_kernel() {
    int i = blockIdx.x * blockDim.x + threadIdx.x;
    if (i < N_NODES) g_cnt[i] = 0;
}

__global__ void count_kernel(const int* __restrict__ dst) {
    int i = blockIdx.x * blockDim.x + threadIdx.x;
    if (i < N_EDGES) atomicAdd(&g_cnt[dst[i]], 1);
}

__global__ void dinv_kernel() {
    int i = blockIdx.x * blockDim.x + threadIdx.x;
    if (i < N_NODES) {
        float deg = (float)g_cnt[i] + 1.0f;
        float di  = rsqrtf(deg);
        g_dinv[i]  = di;
        g_selfn[i] = di * di;
    }
}

// blocked scan: each thread owns a contiguous chunk; shared scan of 1024 sums
__global__ __launch_bounds__(1024)
void scan_kernel() {
    __shared__ int sums[1024];
    const int CH = (N_NODES + 1023) / 1024;   // 49
    int t = threadIdx.x;
    int beg = t * CH;
    int end = min(beg + CH, N_NODES);
    int s = 0;
    for (int i = beg; i < end; i++) s += g_cnt[i];
    sums[t] = s;
    __syncthreads();
    for (int off = 1; off < 1024; off <<= 1) {
        int v = (t >= off) ? sums[t - off] : 0;
        __syncthreads();
        sums[t] += v;
        __syncthreads();
    }
    int excl = sums[t] - s;
    for (int i = beg; i < end; i++) {
        g_off[i] = excl;
        g_cur[i] = excl;
        excl += g_cnt[i];
    }
    if (t == 1023) g_off[N_NODES] = excl;
}

__global__ void fill_kernel(const int* __restrict__ src, const int* __restrict__ dst) {
    int i = blockIdx.x * blockDim.x + threadIdx.x;
    if (i < N_EDGES) {
        int s = src[i], d = dst[i];
        int pos = atomicAdd(&g_cur[d], 1);
        g_srt_src[pos]  = s;
        g_srt_coef[pos] = g_dinv[s] * g_dinv[d];
    }
}

// ---------------- operand packing ------------------------------------------
__global__ void convert_x_kernel(const float* __restrict__ x) {
    size_t i = (size_t)blockIdx.x * blockDim.x + threadIdx.x;
    if (i < (size_t)N_NODES * N_FEAT) {
        float v = x[i];
        __nv_bfloat16 h = __float2bfloat16_rn(v);
        g_xh[i] = h;
        g_xl[i] = __float2bfloat16_rn(v - __bfloat162float(h));
    }
}

// B slabs: per layer l, n-major [512][512]: row n = output col (0-255 gc,
// 256-511 lin), col k. g_Bh[(l*512+n)*512 + k] = W[k][n&255]
__global__ void pack_w_kernel(const float* __restrict__ gcW0,
                              const float* __restrict__ linW0,
                              const float* __restrict__ convsW,
                              const float* __restrict__ linsW) {
    int i = blockIdx.x * blockDim.x + threadIdx.x;
    if (i >= 4 * 512 * 512) return;
    int l = i >> 18, rem = i & 262143, n = rem >> 9, k = rem & 511;
    int Kl = l ? N_HID : N_FEAT;
    if (k >= Kl) return;
    const float* W;
    if (l == 0) W = (n < 256) ? gcW0 : linW0;
    else        W = ((n < 256) ? convsW : linsW) + (l - 1) * N_HID * N_HID;
    float v = W[k * N_HID + (n & 255)];
    __nv_bfloat16 h = __float2bfloat16_rn(v);
    g_Bh[i] = h;
    g_Bl[i] = __float2bfloat16_rn(v - __bfloat162float(h));
}

// ---------------- bf16x3 GEMM: C[M,512] = A[M,K] @ B[K,512] ---------------
// smem per buffer: Ah(10240) Al(10240) Bh(10240) Bl(10240); rows padded to 80B
#define SM_BUF 40960
#define SM_ARR 10240

__device__ __forceinline__ void stage_chunk(
    unsigned sbase, int buf, int k0,
    const __nv_bfloat16* __restrict__ Ah, const __nv_bfloat16* __restrict__ Al,
    const __nv_bfloat16* __restrict__ Bh, const __nv_bfloat16* __restrict__ Bl,
    int row0, int col0, int M, int lda, int tid)
{
    #pragma unroll
    for (int t = 0; t < 8; t++) {
        int i = tid + t * 256;
        int arr = i >> 9, rem = i & 511, r = rem >> 2, c = rem & 3;
        unsigned dst = sbase + buf * SM_BUF + arr * SM_ARR + r * 80 + c * 16;
        const __nv_bfloat16* src;
        unsigned sz = 16;
        if (arr < 2) {
            int gr = row0 + r;
            if (gr >= M) { gr = M - 1; sz = 0; }
            src = (arr ? Al : Ah) + (size_t)gr * lda + k0 + c * 8;
        } else {
            src = ((arr == 2) ? Bh : Bl) + (size_t)(col0 + r) * 512 + k0 + c * 8;
        }
        cp16(dst, src, sz);
    }
}

__global__ __launch_bounds__(256)
void gemm_bf16x3_kernel(const __nv_bfloat16* __restrict__ Ah,
                        const __nv_bfloat16* __restrict__ Al,
                        const __nv_bfloat16* __restrict__ Bh,
                        const __nv_bfloat16* __restrict__ Bl,
                        float* __restrict__ Chw, float* __restrict__ Clin,
                        int M, int K, int lda)
{
    extern __shared__ char smem[];
    const unsigned sbase = su32(smem);
    int tid  = threadIdx.x;
    int lane = tid & 31;
    int wid  = tid >> 5;
    int row0 = blockIdx.y * 128;
    int col0 = blockIdx.x * 128;         // 0..511 over concat(hw,lin)
    int warpM = (wid >> 2) * 64;
    int warpN = (wid & 3) * 32;

    float acc[4][4][4];
    #pragma unroll
    for (int a = 0; a < 4; a++)
        #pragma unroll
        for (int b = 0; b < 4; b++)
            #pragma unroll
            for (int c = 0; c < 4; c++) acc[a][b][c] = 0.f;

    const int nch = K >> 5;
    stage_chunk(sbase, 0, 0, Ah, Al, Bh, Bl, row0, col0, M, lda, tid);
    CP_COMMIT;

    for (int ch = 0; ch < nch; ch++) {
        if (ch + 1 < nch) {
            stage_chunk(sbase, (ch + 1) & 1, (ch + 1) << 5,
                        Ah, Al, Bh, Bl, row0, col0, M, lda, tid);
            CP_COMMIT;
            CP_WAIT1;
        } else {
            CP_WAIT0;
        }
        __syncthreads();

        unsigned abase = sbase + (ch & 1) * SM_BUF;          // Ah; +SM_ARR = Al
        unsigned bbase = abase + 2 * SM_ARR;                 // Bh; +SM_ARR = Bl
        int lrow = lane & 15;
        int lk16 = (lane >> 4) * 16;

        #pragma unroll
        for (int ks = 0; ks < 2; ks++) {
            unsigned ah[4][4], al[4][4];
            #pragma unroll
            for (int mt = 0; mt < 4; mt++) {
                unsigned adr = abase + (warpM + mt * 16 + lrow) * 80 + ks * 32 + lk16;
                LDSM4(ah[mt], adr);
                LDSM4(al[mt], adr + SM_ARR);
            }
            unsigned bh[2][4], bl[2][4];
            #pragma unroll
            for (int g = 0; g < 2; g++) {
                unsigned adr = bbase + (warpN + g * 16 + lrow) * 80 + ks * 32 + lk16;
                LDSM4(bh[g], adr);
                LDSM4(bl[g], adr + SM_ARR);
            }
            #pragma unroll
            for (int mt = 0; mt < 4; mt++)
                #pragma unroll
                for (int nt = 0; nt < 4; nt++) {
                    int g = nt >> 1, o = nt & 1;
                    mma_bf16(acc[mt][nt], ah[mt], bh[g][o], bh[g][2 + o]);
                    mma_bf16(acc[mt][nt], ah[mt], bl[g][o], bl[g][2 + o]);
                    mma_bf16(acc[mt][nt], al[mt], bh[g][o], bh[g][2 + o]);
                }
        }
        __syncthreads();
    }

    // ---- epilogue: direct STG (float2), whole CTA targets one output ----
    float* Cg = (col0 < 256) ? Chw : Clin;
    int cb = (col0 < 256) ? col0 : (col0 - 256);
    #pragma unroll
    for (int mt = 0; mt < 4; mt++)
        #pragma unroll
        for (int nt = 0; nt < 4; nt++) {
            int r = row0 + warpM + mt * 16 + (lane >> 2);
            int c = cb + warpN + nt * 8 + (lane & 3) * 2;
            if (r < M)
                *(float2*)&Cg[(size_t)r * N_HID + c] =
                    make_float2(acc[mt][nt][0], acc[mt][nt][1]);
            if (r + 8 < M)
                *(float2*)&Cg[(size_t)(r + 8) * N_HID + c] =
                    make_float2(acc[mt][nt][2], acc[mt][nt][3]);
        }
}

// ---------------- fused GCN aggregation epilogue ---------------------------
__global__ __launch_bounds__(N_HID)
void agg_kernel(const float* __restrict__ hw, const float* __restrict__ lin,
                const float* __restrict__ gcb, const float* __restrict__ linb,
                int slot)
{
    int n = blockIdx.x;
    int f = threadIdx.x;
    int beg = g_off[n], end = g_off[n + 1];

    float acc = 0.f;
    int e = beg;
    for (; e + 3 < end; e += 4) {
        int   s0 = g_srt_src[e],     s1 = g_srt_src[e + 1];
        int   s2 = g_srt_src[e + 2], s3 = g_srt_src[e + 3];
        float c0 = g_srt_coef[e],     c1 = g_srt_coef[e + 1];
        float c2 = g_srt_coef[e + 2], c3 = g_srt_coef[e + 3];
        acc += c0 * hw[s0 * N_HID + f];
        acc += c1 * hw[s1 * N_HID + f];
        acc += c2 * hw[s2 * N_HID + f];
        acc += c3 * hw[s3 * N_HID + f];
    }
    for (; e < end; e++)
        acc += g_srt_coef[e] * hw[g_srt_src[e] * N_HID + f];

    float r = acc + g_selfn[n] * hw[n * N_HID + f] + gcb[f]
              + lin[n * N_HID + f] + linb[f];
    float rm = fmaxf(r, 0.f);
    g_jk[(size_t)n * JK_DIM + slot * N_HID + f] = rm;
    if (slot < N_LAYER - 1) {
        __nv_bfloat16 h = __float2bfloat16_rn(rm);
        g_Ah[(size_t)n * N_HID + f] = h;
        g_Al[(size_t)n * N_HID + f] = __float2bfloat16_rn(rm - __bfloat162float(h));
    }
}

// ---------------- output GEMM: [50000,1024] @ [1024,40] + bias ------------
__global__ __launch_bounds__(320)
void out_gemm_kernel(const float* __restrict__ W, const float* __restrict__ b,
                     float* __restrict__ out)
{
    __shared__ float shA[32][65];
    __shared__ float shW[64][N_CLASS];
    int t = threadIdx.x;
    int row0 = blockIdx.x * 32;
    int c  = t % N_CLASS;
    int r8 = t / N_CLASS;

    float acc[4] = {0.f, 0.f, 0.f, 0.f};

    for (int k0 = 0; k0 < JK_DIM; k0 += 64) {
        for (int l = t; l < 32 * 64; l += 320) {
            int r = l >> 6, kk = l & 63;
            int gr = row0 + r;
            shA[r][kk] = (gr < N_NODES) ? g_jk[(size_t)gr * JK_DIM + k0 + kk] : 0.f;
        }
        for (int l = t; l < 64 * N_CLASS; l += 320) {
            int kk = l / N_CLASS, cc = l % N_CLASS;
            shW[kk][cc] = W[(k0 + kk) * N_CLASS + cc];
        }
        __syncthreads();
        #pragma unroll 8
        for (int kk = 0; kk < 64; kk++) {
            float w = shW[kk][c];
            #pragma unroll
            for (int j = 0; j < 4; j++)
                acc[j] += shA[r8 + 8 * j][kk] * w;
        }
        __syncthreads();
    }

    float bb = b[c];
    #pragma unroll
    for (int j = 0; j < 4; j++) {
        int gr = row0 + r8 + 8 * j;
        if (gr < N_NODES) out[gr * N_CLASS + c] = acc[j] + bb;
    }
}

// ---------------- launch ---------------------------------------------------
extern "C" void kernel_launch(void* const* d_in, const int* in_sizes, int n_in,
                              void* d_out, int out_size)
{
    const float* x        = (const float*)d_in[0];
    const int*   edge     = (const int*)  d_in[1];
    const float* in_gc_W  = (const float*)d_in[2];
    const float* in_gc_b  = (const float*)d_in[3];
    const float* in_lin_W = (const float*)d_in[4];
    const float* in_lin_b = (const float*)d_in[5];
    const float* convs_W  = (const float*)d_in[6];
    const float* convs_b  = (const float*)d_in[7];
    const float* lins_W   = (const float*)d_in[8];
    const float* lins_b   = (const float*)d_in[9];
    const float* out_W    = (const float*)d_in[10];
    const float* out_b    = (const float*)d_in[11];
    float*       out      = (float*)d_out;

    const int* src = edge;
    const int* dst = edge + N_EDGES;

    float *p_hw, *p_lin, *p_jk;
    cudaGetSymbolAddress((void**)&p_hw,  g_hw);
    cudaGetSymbolAddress((void**)&p_lin, g_lin);
    cudaGetSymbolAddress((void**)&p_jk,  g_jk);
    __nv_bfloat16 *p_xh, *p_xl, *p_Ah, *p_Al, *p_Bh, *p_Bl;
    cudaGetSymbolAddress((void**)&p_xh, g_xh);
    cudaGetSymbolAddress((void**)&p_xl, g_xl);
    cudaGetSymbolAddress((void**)&p_Ah, g_Ah);
    cudaGetSymbolAddress((void**)&p_Al, g_Al);
    cudaGetSymbolAddress((void**)&p_Bh, g_Bh);
    cudaGetSymbolAddress((void**)&p_Bl, g_Bl);

    cudaFuncSetAttribute(gemm_bf16x3_kernel,
                         cudaFuncAttributeMaxDynamicSharedMemorySize, 2 * SM_BUF);

    // --- preprocessing: degrees, normalization, CSR-by-dst sort ---
    zero_cnt_kernel<<<(N_NODES + 255) / 256, 256>>>();
    count_kernel<<<(N_EDGES + 255) / 256, 256>>>(dst);
    dinv_kernel<<<(N_NODES + 255) / 256, 256>>>();
    scan_kernel<<<1, 1024>>>();
    fill_kernel<<<(N_EDGES + 255) / 256, 256>>>(src, dst);

    // --- operand packing ---
    convert_x_kernel<<<(N_NODES * N_FEAT + 255) / 256, 256>>>(x);
    pack_w_kernel<<<(4 * 512 * 512 + 255) / 256, 256>>>(in_gc_W, in_lin_W,
                                                        convs_W, lins_W);

    dim3 ggrid(4, (N_NODES + 127) / 128);   // N=512 concat, M blocks

    // --- layer 0: K=512, A = x (hi/lo) ---
    gemm_bf16x3_kernel<<<ggrid, 256, 2 * SM_BUF>>>(
        p_xh, p_xl, p_Bh, p_Bl, p_hw, p_lin, N_NODES, N_FEAT, N_FEAT);
    agg_kernel<<<N_NODES, N_HID>>>(p_hw, p_lin, in_gc_b, in_lin_b, 0);

    // --- layers 1..3: K=256, A = previous relu output (hi/lo) ---
    for (int i = 0; i < N_LAYER - 1; i++) {
        gemm_bf16x3_kernel<<<ggrid, 256, 2 * SM_BUF>>>(
            p_Ah, p_Al, p_Bh + (size_t)(i + 1) * 512 * 512,
            p_Bl + (size_t)(i + 1) * 512 * 512,
            p_hw, p_lin, N_NODES, N_HID, N_HID);
        agg_kernel<<<N_NODES, N_HID>>>(p_hw, p_lin,
                                       convs_b + i * N_HID, lins_b + i * N_HID,
                                       i + 1);
    }

    // --- output projection ---
    out_gemm_kernel<<<(N_NODES + 31) / 32, 320>>>(out_W, out_b, out);
}

// round 4
// speedup vs baseline: 3.2576x; 1.3199x over previous
#include <cuda_runtime.h>
#include <cuda_bf16.h>

#define N_NODES 50000
#define N_EDGES 800000
#define N_FEAT  512
#define N_HID   256
#define N_LAYER 4
#define N_CLASS 40
#define JK_DIM  (N_HID * N_LAYER)   // 1024

// ---------------- scratch (device globals; no allocation allowed) ----------
__device__ int   g_cnt[N_NODES];
__device__ int   g_off[N_NODES + 1];
__device__ int   g_cur[N_NODES];
__device__ int   g_bsum[16];
__device__ int   g_boff[16];
__device__ int   g_srt_src[N_EDGES];
__device__ float g_srt_coef[N_EDGES];
__device__ float g_dinv[N_NODES];
__device__ float g_selfn[N_NODES];
__device__ __align__(256) float g_hw [N_NODES * N_HID];            // 51.2 MB
__device__ __align__(256) float g_lin[N_NODES * N_HID];            // 51.2 MB
// JK slab in bf16 hi/lo (same bytes as one fp32 slab)
__device__ __align__(256) __nv_bfloat16 g_jkh[(size_t)N_NODES * JK_DIM];
__device__ __align__(256) __nv_bfloat16 g_jkl[(size_t)N_NODES * JK_DIM];
__device__ __align__(256) __nv_bfloat16 g_xh[(size_t)N_NODES * N_FEAT];
__device__ __align__(256) __nv_bfloat16 g_xl[(size_t)N_NODES * N_FEAT];
__device__ __align__(256) __nv_bfloat16 g_Bh[4 * 512 * 512];
__device__ __align__(256) __nv_bfloat16 g_Bl[4 * 512 * 512];
__device__ __align__(256) __nv_bfloat16 g_Woh[64 * JK_DIM];
__device__ __align__(256) __nv_bfloat16 g_Wol[64 * JK_DIM];

// ---------------- helpers ---------------------------------------------------
__device__ __forceinline__ unsigned su32(const void* p) {
    unsigned a;
    asm("{ .reg .u64 t; cvta.to.shared.u64 t, %1; cvt.u32.u64 %0, t; }"
        : "=r"(a) : "l"(p));
    return a;
}

__device__ __forceinline__ void cp16(unsigned d, const void* s, unsigned sz) {
    asm volatile("cp.async.cg.shared.global [%0], [%1], 16, %2;"
                 :: "r"(d), "l"(s), "r"(sz) : "memory");
}
#define CP_COMMIT asm volatile("cp.async.commit_group;" ::: "memory")
#define CP_WAIT1  asm volatile("cp.async.wait_group 1;" ::: "memory")
#define CP_WAIT0  asm volatile("cp.async.wait_group 0;" ::: "memory")

#define LDSM4(r, a) \
    asm volatile("ldmatrix.sync.aligned.m8n8.x4.shared.b16 {%0,%1,%2,%3}, [%4];" \
        : "=r"((r)[0]), "=r"((r)[1]), "=r"((r)[2]), "=r"((r)[3]) : "r"(a))

__device__ __forceinline__ void mma_bf16(float* c, const unsigned* a,
                                         unsigned b0, unsigned b1) {
    asm volatile("mma.sync.aligned.m16n8k16.row.col.f32.bf16.bf16.f32 "
        "{%0,%1,%2,%3}, {%4,%5,%6,%7}, {%8,%9}, {%0,%1,%2,%3};"
        : "+f"(c[0]), "+f"(c[1]), "+f"(c[2]), "+f"(c[3])
        : "r"(a[0]), "r"(a[1]), "r"(a[2]), "r"(a[3]), "r"(b0), "r"(b1));
}

// ---------------- preprocessing kernels -----------------------------------
__global__ void zero_cnt_kernel() {
    int i = blockIdx.x * blockDim.x + threadIdx.x;
    if (i < N_NODES) g_cnt[i] = 0;
}

__global__ void count_kernel(const int* __restrict__ dst) {
    int i = blockIdx.x * blockDim.x + threadIdx.x;
    if (i < N_EDGES) atomicAdd(&g_cnt[dst[i]], 1);
}

__global__ void dinv_kernel() {
    int i = blockIdx.x * blockDim.x + threadIdx.x;
    if (i < N_NODES) {
        float deg = (float)g_cnt[i] + 1.0f;
        float di  = rsqrtf(deg);
        g_dinv[i]  = di;
        g_selfn[i] = di * di;
    }
}

// --- coalesced 3-phase scan: 13 blocks x 4096 elems each ---
__global__ __launch_bounds__(1024)
void scan1_kernel() {
    __shared__ int sh[1024];
    int b = blockIdx.x, t = threadIdx.x;
    int idx = b * 4096 + t * 4;
    int s = 0;
    if (idx + 3 < N_NODES) {
        int4 v = *(const int4*)&g_cnt[idx];
        s = v.x + v.y + v.z + v.w;
    } else {
        for (int j = 0; j < 4; j++) if (idx + j < N_NODES) s += g_cnt[idx + j];
    }
    sh[t] = s;
    __syncthreads();
    for (int off = 512; off > 0; off >>= 1) {
        if (t < off) sh[t] += sh[t + off];
        __syncthreads();
    }
    if (t == 0) g_bsum[b] = sh[0];
}

__global__ void scan2_kernel(int nblk) {
    if (threadIdx.x == 0) {
        int acc = 0;
        for (int i = 0; i < nblk; i++) { g_boff[i] = acc; acc += g_bsum[i]; }
        g_off[N_NODES] = acc;
    }
}

__global__ __launch_bounds__(1024)
void scan3_kernel() {
    __shared__ int sh[1024];
    int b = blockIdx.x, t = threadIdx.x;
    int idx = b * 4096 + t * 4;
    int c0 = 0, c1 = 0, c2 = 0, c3 = 0;
    if (idx + 3 < N_NODES) {
        int4 v = *(const int4*)&g_cnt[idx];
        c0 = v.x; c1 = v.y; c2 = v.z; c3 = v.w;
    } else {
        if (idx + 0 < N_NODES) c0 = g_cnt[idx + 0];
        if (idx + 1 < N_NODES) c1 = g_cnt[idx + 1];
        if (idx + 2 < N_NODES) c2 = g_cnt[idx + 2];
        if (idx + 3 < N_NODES) c3 = g_cnt[idx + 3];
    }
    int s = c0 + c1 + c2 + c3;
    sh[t] = s;
    __syncthreads();
    for (int off = 1; off < 1024; off <<= 1) {
        int v = (t >= off) ? sh[t - off] : 0;
        __syncthreads();
        sh[t] += v;
        __syncthreads();
    }
    int excl = g_boff[b] + sh[t] - s;
    int4 ov = make_int4(excl, excl + c0, excl + c0 + c1, excl + c0 + c1 + c2);
    if (idx + 3 < N_NODES) {
        *(int4*)&g_off[idx] = ov;
        *(int4*)&g_cur[idx] = ov;
    } else {
        int o[4] = {ov.x, ov.y, ov.z, ov.w};
        for (int j = 0; j < 4; j++)
            if (idx + j < N_NODES) { g_off[idx + j] = o[j]; g_cur[idx + j] = o[j]; }
    }
}

__global__ void fill_kernel(const int* __restrict__ src, const int* __restrict__ dst) {
    int i = blockIdx.x * blockDim.x + threadIdx.x;
    if (i < N_EDGES) {
        int s = src[i], d = dst[i];
        int pos = atomicAdd(&g_cur[d], 1);
        g_srt_src[pos]  = s;
        g_srt_coef[pos] = g_dinv[s] * g_dinv[d];
    }
}

// ---------------- operand packing ------------------------------------------
__global__ void convert_x_kernel(const float* __restrict__ x) {
    size_t i = ((size_t)blockIdx.x * blockDim.x + threadIdx.x) * 4;
    if (i >= (size_t)N_NODES * N_FEAT) return;
    float4 v = *(const float4*)(x + i);
    __nv_bfloat162 h01, h23, l01, l23;
    h01.x = __float2bfloat16_rn(v.x); h01.y = __float2bfloat16_rn(v.y);
    h23.x = __float2bfloat16_rn(v.z); h23.y = __float2bfloat16_rn(v.w);
    l01.x = __float2bfloat16_rn(v.x - __bfloat162float(h01.x));
    l01.y = __float2bfloat16_rn(v.y - __bfloat162float(h01.y));
    l23.x = __float2bfloat16_rn(v.z - __bfloat162float(h23.x));
    l23.y = __float2bfloat16_rn(v.w - __bfloat162float(h23.y));
    *(uint2*)&g_xh[i] = make_uint2(*(unsigned*)&h01, *(unsigned*)&h23);
    *(uint2*)&g_xl[i] = make_uint2(*(unsigned*)&l01, *(unsigned*)&l23);
}

// B slabs: per layer l, n-major [512][512]; row n = output col (0-255 gc,
// 256-511 lin), col k. g_Bh[(l*512+n)*512 + k] = W[k][n&255]
__global__ void pack_w_kernel(const float* __restrict__ gcW0,
                              const float* __restrict__ linW0,
                              const float* __restrict__ convsW,
                              const float* __restrict__ linsW) {
    int i = blockIdx.x * blockDim.x + threadIdx.x;
    if (i >= 4 * 512 * 512) return;
    int l = i >> 18, rem = i & 262143, n = rem >> 9, k = rem & 511;
    int Kl = l ? N_HID : N_FEAT;
    if (k >= Kl) return;
    const float* W;
    if (l == 0) W = (n < 256) ? gcW0 : linW0;
    else        W = ((n < 256) ? convsW : linsW) + (l - 1) * N_HID * N_HID;
    float v = W[k * N_HID + (n & 255)];
    __nv_bfloat16 h = __float2bfloat16_rn(v);
    g_Bh[i] = h;
    g_Bl[i] = __float2bfloat16_rn(v - __bfloat162float(h));
}

// out_W packed n-major [64][1024], rows 40..63 zero
__global__ void pack_wo_kernel(const float* __restrict__ outW) {
    int i = blockIdx.x * blockDim.x + threadIdx.x;
    if (i >= 64 * JK_DIM) return;
    int n = i >> 10, k = i & 1023;
    float v = (n < N_CLASS) ? outW[k * N_CLASS + n] : 0.f;
    __nv_bfloat16 h = __float2bfloat16_rn(v);
    g_Woh[i] = h;
    g_Wol[i] = __float2bfloat16_rn(v - __bfloat162float(h));
}

// ---------------- bf16x3 GEMM: C[M,512] = A[M,K] @ B[K,512] ---------------
#define SM_BUF 40960
#define SM_ARR 10240

__device__ __forceinline__ void stage_chunk(
    unsigned sbase, int buf, int k0,
    const __nv_bfloat16* __restrict__ Ah, const __nv_bfloat16* __restrict__ Al,
    const __nv_bfloat16* __restrict__ Bh, const __nv_bfloat16* __restrict__ Bl,
    int row0, int col0, int M, int lda, int tid)
{
    #pragma unroll
    for (int t = 0; t < 8; t++) {
        int i = tid + t * 256;
        int arr = i >> 9, rem = i & 511, r = rem >> 2, c = rem & 3;
        unsigned dst = sbase + buf * SM_BUF + arr * SM_ARR + r * 80 + c * 16;
        const __nv_bfloat16* src;
        unsigned sz = 16;
        if (arr < 2) {
            int gr = row0 + r;
            if (gr >= M) { gr = M - 1; sz = 0; }
            src = (arr ? Al : Ah) + (size_t)gr * lda + k0 + c * 8;
        } else {
            src = ((arr == 2) ? Bh : Bl) + (size_t)(col0 + r) * 512 + k0 + c * 8;
        }
        cp16(dst, src, sz);
    }
}

__global__ __launch_bounds__(256)
void gemm_bf16x3_kernel(const __nv_bfloat16* __restrict__ Ah,
                        const __nv_bfloat16* __restrict__ Al,
                        const __nv_bfloat16* __restrict__ Bh,
                        const __nv_bfloat16* __restrict__ Bl,
                        float* __restrict__ Chw, float* __restrict__ Clin,
                        int M, int K, int lda)
{
    extern __shared__ char smem[];
    const unsigned sbase = su32(smem);
    int tid  = threadIdx.x;
    int lane = tid & 31;
    int wid  = tid >> 5;
    int row0 = blockIdx.y * 128;
    int col0 = blockIdx.x * 128;
    int warpM = (wid >> 2) * 64;
    int warpN = (wid & 3) * 32;

    float acc[4][4][4];
    #pragma unroll
    for (int a = 0; a < 4; a++)
        #pragma unroll
        for (int b = 0; b < 4; b++)
            #pragma unroll
            for (int c = 0; c < 4; c++) acc[a][b][c] = 0.f;

    const int nch = K >> 5;
    stage_chunk(sbase, 0, 0, Ah, Al, Bh, Bl, row0, col0, M, lda, tid);
    CP_COMMIT;

    for (int ch = 0; ch < nch; ch++) {
        if (ch + 1 < nch) {
            stage_chunk(sbase, (ch + 1) & 1, (ch + 1) << 5,
                        Ah, Al, Bh, Bl, row0, col0, M, lda, tid);
            CP_COMMIT;
            CP_WAIT1;
        } else {
            CP_WAIT0;
        }
        __syncthreads();

        unsigned abase = sbase + (ch & 1) * SM_BUF;
        unsigned bbase = abase + 2 * SM_ARR;
        int lrow = lane & 15;
        int lk16 = (lane >> 4) * 16;

        #pragma unroll
        for (int ks = 0; ks < 2; ks++) {
            unsigned ah[4][4], al[4][4];
            #pragma unroll
            for (int mt = 0; mt < 4; mt++) {
                unsigned adr = abase + (warpM + mt * 16 + lrow) * 80 + ks * 32 + lk16;
                LDSM4(ah[mt], adr);
                LDSM4(al[mt], adr + SM_ARR);
            }
            unsigned bh[2][4], bl[2][4];
            #pragma unroll
            for (int g = 0; g < 2; g++) {
                unsigned adr = bbase + (warpN + g * 16 + lrow) * 80 + ks * 32 + lk16;
                LDSM4(bh[g], adr);
                LDSM4(bl[g], adr + SM_ARR);
            }
            #pragma unroll
            for (int mt = 0; mt < 4; mt++)
                #pragma unroll
                for (int nt = 0; nt < 4; nt++) {
                    int g = nt >> 1, o = nt & 1;
                    mma_bf16(acc[mt][nt], ah[mt], bh[g][o], bh[g][2 + o]);
                    mma_bf16(acc[mt][nt], ah[mt], bl[g][o], bl[g][2 + o]);
                    mma_bf16(acc[mt][nt], al[mt], bh[g][o], bh[g][2 + o]);
                }
        }
        __syncthreads();
    }

    float* Cg = (col0 < 256) ? Chw : Clin;
    int cb = (col0 < 256) ? col0 : (col0 - 256);
    #pragma unroll
    for (int mt = 0; mt < 4; mt++)
        #pragma unroll
        for (int nt = 0; nt < 4; nt++) {
            int r = row0 + warpM + mt * 16 + (lane >> 2);
            int c = cb + warpN + nt * 8 + (lane & 3) * 2;
            if (r < M)
                *(float2*)&Cg[(size_t)r * N_HID + c] =
                    make_float2(acc[mt][nt][0], acc[mt][nt][1]);
            if (r + 8 < M)
                *(float2*)&Cg[(size_t)(r + 8) * N_HID + c] =
                    make_float2(acc[mt][nt][2], acc[mt][nt][3]);
        }
}

// ---------------- fused GCN aggregation epilogue ---------------------------
__global__ __launch_bounds__(N_HID)
void agg_kernel(const float* __restrict__ hw, const float* __restrict__ lin,
                const float* __restrict__ gcb, const float* __restrict__ linb,
                int slot)
{
    int n = blockIdx.x;
    int f = threadIdx.x;
    int beg = g_off[n], end = g_off[n + 1];

    float acc = 0.f;
    int e = beg;
    for (; e + 3 < end; e += 4) {
        int   s0 = g_srt_src[e],     s1 = g_srt_src[e + 1];
        int   s2 = g_srt_src[e + 2], s3 = g_srt_src[e + 3];
        float c0 = g_srt_coef[e],     c1 = g_srt_coef[e + 1];
        float c2 = g_srt_coef[e + 2], c3 = g_srt_coef[e + 3];
        acc += c0 * hw[s0 * N_HID + f];
        acc += c1 * hw[s1 * N_HID + f];
        acc += c2 * hw[s2 * N_HID + f];
        acc += c3 * hw[s3 * N_HID + f];
    }
    for (; e < end; e++)
        acc += g_srt_coef[e] * hw[g_srt_src[e] * N_HID + f];

    float r = acc + g_selfn[n] * hw[n * N_HID + f] + gcb[f]
              + lin[n * N_HID + f] + linb[f];
    float rm = fmaxf(r, 0.f);
    __nv_bfloat16 h = __float2bfloat16_rn(rm);
    size_t o = (size_t)n * JK_DIM + slot * N_HID + f;
    g_jkh[o] = h;
    g_jkl[o] = __float2bfloat16_rn(rm - __bfloat162float(h));
}

// ---------------- output GEMM via bf16x3 HMMA ------------------------------
// C[50000,40] = jk[50000,1024] @ outW[1024,40]; N padded to 64, 5 n8-tiles used
#define OSM_A  10240            // 128 rows x 80B
#define OSM_B  5120             // 64 rows x 80B
#define OSM_BUF (2 * OSM_A + 2 * OSM_B)   // 30720

__global__ __launch_bounds__(256)
void out_mma_kernel(const float* __restrict__ bias, float* __restrict__ out)
{
    extern __shared__ char smem[];
    const unsigned sbase = su32(smem);
    int tid  = threadIdx.x;
    int lane = tid & 31;
    int wid  = tid >> 5;
    int row0 = blockIdx.x * 128;

    float acc[5][4];
    #pragma unroll
    for (int a = 0; a < 5; a++)
        #pragma unroll
        for (int c = 0; c < 4; c++) acc[a][c] = 0.f;

    // stage one 32-k chunk
    auto stage = [&](int buf, int k0) {
        #pragma unroll
        for (int t = 0; t < 6; t++) {
            int i = tid + t * 256;
            unsigned dst; const __nv_bfloat16* src; unsigned sz = 16;
            if (i < 1024) {
                int hl = i >> 9, rem = i & 511, r = rem >> 2, c = rem & 3;
                int gr = row0 + r;
                if (gr >= N_NODES) { gr = N_NODES - 1; sz = 0; }
                src = (hl ? g_jkl : g_jkh) + (size_t)gr * JK_DIM + k0 + c * 8;
                dst = sbase + buf * OSM_BUF + hl * OSM_A + r * 80 + c * 16;
            } else {
                int j = i - 1024;
                int hl = j >> 8, rem = j & 255, r = rem >> 2, c = rem & 3;
                src = (hl ? g_Wol : g_Woh) + (size_t)r * JK_DIM + k0 + c * 8;
                dst = sbase + buf * OSM_BUF + 2 * OSM_A + hl * OSM_B + r * 80 + c * 16;
            }
            cp16(dst, src, sz);
        }
    };

    stage(0, 0);
    CP_COMMIT;

    const int nch = JK_DIM / 32;     // 32
    for (int ch = 0; ch < nch; ch++) {
        if (ch + 1 < nch) {
            stage((ch + 1) & 1, (ch + 1) * 32);
            CP_COMMIT;
            CP_WAIT1;
        } else {
            CP_WAIT0;
        }
        __syncthreads();

        unsigned abase = sbase + (ch & 1) * OSM_BUF;
        unsigned bbase = abase + 2 * OSM_A;
        int lrow = lane & 15;
        int lk16 = (lane >> 4) * 16;

        #pragma unroll
        for (int ks = 0; ks < 2; ks++) {
            unsigned ah[4], al[4];
            unsigned adr = abase + (wid * 16 + lrow) * 80 + ks * 32 + lk16;
            LDSM4(ah, adr);
            LDSM4(al, adr + OSM_A);
            unsigned bh[3][4], bl[3][4];
            #pragma unroll
            for (int g = 0; g < 3; g++) {
                unsigned badr = bbase + (g * 16 + lrow) * 80 + ks * 32 + lk16;
                LDSM4(bh[g], badr);
                LDSM4(bl[g], badr + OSM_B);
            }
            #pragma unroll
            for (int nt = 0; nt < 5; nt++) {
                int g = nt >> 1, o = nt & 1;
                mma_bf16(acc[nt], ah, bh[g][o], bh[g][2 + o]);
                mma_bf16(acc[nt], ah, bl[g][o], bl[g][2 + o]);
                mma_bf16(acc[nt], al, bh[g][o], bh[g][2 + o]);
            }
        }
        __syncthreads();
    }

    // epilogue: rows wid*16 + lane/4 (+8), cols nt*8 + (lane&3)*2
    #pragma unroll
    for (int nt = 0; nt < 5; nt++) {
        int c = nt * 8 + (lane & 3) * 2;
        float2 bv = make_float2(bias[c], bias[c + 1]);
        int r = row0 + wid * 16 + (lane >> 2);
        if (r < N_NODES)
            *(float2*)&out[(size_t)r * N_CLASS + c] =
                make_float2(acc[nt][0] + bv.x, acc[nt][1] + bv.y);
        if (r + 8 < N_NODES)
            *(float2*)&out[(size_t)(r + 8) * N_CLASS + c] =
                make_float2(acc[nt][2] + bv.x, acc[nt][3] + bv.y);
    }
}

// ---------------- launch ---------------------------------------------------
extern "C" void kernel_launch(void* const* d_in, const int* in_sizes, int n_in,
                              void* d_out, int out_size)
{
    const float* x        = (const float*)d_in[0];
    const int*   edge     = (const int*)  d_in[1];
    const float* in_gc_W  = (const float*)d_in[2];
    const float* in_gc_b  = (const float*)d_in[3];
    const float* in_lin_W = (const float*)d_in[4];
    const float* in_lin_b = (const float*)d_in[5];
    const float* convs_W  = (const float*)d_in[6];
    const float* convs_b  = (const float*)d_in[7];
    const float* lins_W   = (const float*)d_in[8];
    const float* lins_b   = (const float*)d_in[9];
    const float* out_W    = (const float*)d_in[10];
    const float* out_b    = (const float*)d_in[11];
    float*       out      = (float*)d_out;

    const int* src = edge;
    const int* dst = edge + N_EDGES;

    float *p_hw, *p_lin;
    cudaGetSymbolAddress((void**)&p_hw,  g_hw);
    cudaGetSymbolAddress((void**)&p_lin, g_lin);
    __nv_bfloat16 *p_xh, *p_xl, *p_jkh, *p_jkl, *p_Bh, *p_Bl;
    cudaGetSymbolAddress((void**)&p_xh,  g_xh);
    cudaGetSymbolAddress((void**)&p_xl,  g_xl);
    cudaGetSymbolAddress((void**)&p_jkh, g_jkh);
    cudaGetSymbolAddress((void**)&p_jkl, g_jkl);
    cudaGetSymbolAddress((void**)&p_Bh,  g_Bh);
    cudaGetSymbolAddress((void**)&p_Bl,  g_Bl);

    cudaFuncSetAttribute(gemm_bf16x3_kernel,
                         cudaFuncAttributeMaxDynamicSharedMemorySize, 2 * SM_BUF);
    cudaFuncSetAttribute(out_mma_kernel,
                         cudaFuncAttributeMaxDynamicSharedMemorySize, 2 * OSM_BUF);

    dim3 ggrid(4, (N_NODES + 127) / 128);

    // order chosen so gemm layer0 lands at overall launch index 5 (ncu -s 5)
    convert_x_kernel<<<(N_NODES * N_FEAT / 4 + 255) / 256, 256>>>(x);
    pack_w_kernel<<<(4 * 512 * 512 + 255) / 256, 256>>>(in_gc_W, in_lin_W,
                                                        convs_W, lins_W);
    zero_cnt_kernel<<<(N_NODES + 255) / 256, 256>>>();
    gemm_bf16x3_kernel<<<ggrid, 256, 2 * SM_BUF>>>(      // <- profiled
        p_xh, p_xl, p_Bh, p_Bl, p_hw, p_lin, N_NODES, N_FEAT, N_FEAT);
    pack_wo_kernel<<<(64 * JK_DIM + 255) / 256, 256>>>(out_W);
    count_kernel<<<(N_EDGES + 255) / 256, 256>>>(dst);
    dinv_kernel<<<(N_NODES + 255) / 256, 256>>>();
    scan1_kernel<<<13, 1024>>>();
    scan2_kernel<<<1, 32>>>(13);
    scan3_kernel<<<13, 1024>>>();
    fill_kernel<<<(N_EDGES + 255) / 256, 256>>>(src, dst);

    agg_kernel<<<N_NODES, N_HID>>>(p_hw, p_lin, in_gc_b, in_lin_b, 0);

    for (int i = 0; i < N_LAYER - 1; i++) {
        gemm_bf16x3_kernel<<<ggrid, 256, 2 * SM_BUF>>>(
            p_jkh + i * N_HID, p_jkl + i * N_HID,
            p_Bh + (size_t)(i + 1) * 512 * 512,
            p_Bl + (size_t)(i + 1) * 512 * 512,
            p_hw, p_lin, N_NODES, N_HID, JK_DIM);
        agg_kernel<<<N_NODES, N_HID>>>(p_hw, p_lin,
                                       convs_b + i * N_HID, lins_b + i * N_HID,
                                       i + 1);
    }

    out_mma_kernel<<<(N_NODES + 127) / 128, 256, 2 * OSM_BUF>>>(out_b, out);
}